// round 15
// baseline (speedup 1.0000x reference)
#include <cuda_runtime.h>
#include <cuda_fp16.h>
#include <cstdint>
#include <cstddef>

// Problem dims
#define NTOK 1024
#define DIM  1024
#define VOC  32000
#define NKF  8
#define KTOT (NKF * DIM)            // 8192

// GEMM tiling
#define MT 128                      // token rows per CTA
#define NV 128                      // vocab cols per CTA
#define KT 64                       // k halves per stage (= 128 B per row, SW128)
#define NKIT (KTOT / KT)            // 128 k-iterations
#define STAGES 3
#define NPAN (VOC / NV)             // 250 vocab panels
#define MINI 38                     // panels converted serially (covers wave 1)
#define NPROD (NPAN - MINI)         // 212 woven-converted panels (< 296 slots)

// SMEM layout (dynamic)
#define SM_BIAS 0                                   // 8*128 floats = 4096 B
#define SM_TILE 4096
#define STAGE_A_BYTES (MT * 128)                    // 16384
#define STAGE_B_BYTES (NV * 128)                    // 16384
#define STAGE_BYTES (STAGE_A_BYTES + STAGE_B_BYTES) // 32768
#define SM_A(s) (SM_TILE + (s) * STAGE_BYTES)
#define SM_B(s) (SM_A(s) + STAGE_A_BYTES)
#define SMEM_TOTAL (SM_TILE + STAGES * STAGE_BYTES) // 102400 -> 2 CTAs/SM

// ---------------- static device scratch (no cudaMalloc allowed) -------------
__device__ __align__(1024) __half g_Wf16T[(size_t)VOC * KTOT];   // [v][k*D+d]
__device__ __align__(1024) __half g_Xt[(size_t)NTOK * KTOT];     // [n][k*D+d]
__device__ float g_gate[NTOK * NKF];
__device__ int g_flags[256];                                     // per-panel ready

// ---------------- PTX helpers ------------------------------------------------
__device__ __forceinline__ uint32_t smem_u32(const void* p) {
    uint32_t a;
    asm("{ .reg .u64 t; cvta.to.shared.u64 t, %1; cvt.u32.u64 %0, t; }"
        : "=r"(a) : "l"(p));
    return a;
}
__device__ __forceinline__ void cp16(uint32_t dst, const void* src) {
    asm volatile("cp.async.cg.shared.global [%0], [%1], 16;"
                 :: "r"(dst), "l"(__cvta_generic_to_global(src)) : "memory");
}
__device__ __forceinline__ void cp_commit() {
    asm volatile("cp.async.commit_group;" ::: "memory");
}
template <int N>
__device__ __forceinline__ void cp_wait() {
    asm volatile("cp.async.wait_group %0;" :: "n"(N) : "memory");
}
__device__ __forceinline__ void ldm_x4(uint32_t& r0, uint32_t& r1, uint32_t& r2,
                                       uint32_t& r3, uint32_t addr) {
    asm volatile("ldmatrix.sync.aligned.m8n8.x4.shared.b16 {%0,%1,%2,%3}, [%4];"
                 : "=r"(r0), "=r"(r1), "=r"(r2), "=r"(r3) : "r"(addr));
}
__device__ __forceinline__ void mma16816(float* c, const uint32_t* a,
                                         const uint32_t* b) {
    asm volatile(
        "mma.sync.aligned.m16n8k16.row.col.f32.f16.f16.f32 "
        "{%0,%1,%2,%3}, {%4,%5,%6,%7}, {%8,%9}, {%0,%1,%2,%3};"
        : "+f"(c[0]), "+f"(c[1]), "+f"(c[2]), "+f"(c[3])
        : "r"(a[0]), "r"(a[1]), "r"(a[2]), "r"(a[3]), "r"(b[0]), "r"(b[1]));
}
__device__ __forceinline__ uint32_t sw128(uint32_t off) {
    return off ^ ((off >> 3) & 0x70);
}

// ---------------- kernel 1: mini convert (panels 0..MINI-1 only) ------------
__global__ void __launch_bounds__(256) convert_wf_kernel(const float* __restrict__ Wf) {
    size_t gid = (size_t)blockIdx.x * 256 + threadIdx.x;   // one 8-half chunk
    if (gid >= (size_t)MINI * NV * KTOT / 8) return;
    size_t o = gid * 8;                // output half index
    int v = (int)(o >> 13);            // / 8192
    int rem = (int)(o & (KTOT - 1));
    int k = rem >> 10;
    int d = rem & (DIM - 1);
    const float4* src = reinterpret_cast<const float4*>(
        Wf + ((size_t)k * VOC + v) * DIM + d);
    float4 a = src[0], b = src[1];
    __half2 h[4];
    h[0] = __floats2half2_rn(a.x, a.y);
    h[1] = __floats2half2_rn(a.z, a.w);
    h[2] = __floats2half2_rn(b.x, b.y);
    h[3] = __floats2half2_rn(b.z, b.w);
    *reinterpret_cast<uint4*>(g_Wf16T + o) = *reinterpret_cast<uint4*>(h);
}

// ---------------- kernel 2: gate softmax + Xt = g*x (fp16) + flag clear -----
__global__ void __launch_bounds__(256) gate_kernel(const float* __restrict__ x,
                                                   const float* __restrict__ Wg,
                                                   const float* __restrict__ bg) {
    __shared__ float x_s[DIM];
    __shared__ float logit_s[NKF];
    int n = blockIdx.x;
    int tid = threadIdx.x;
    int w = tid >> 5, lane = tid & 31;

    if (n == 0) g_flags[tid] = 0;      // reset panel flags every launch

    const float* xr = x + (size_t)n * DIM;
    for (int i = tid; i < DIM; i += 256) x_s[i] = xr[i];
    __syncthreads();

    float s = 0.f;
    const float* wr = Wg + w * DIM;
    #pragma unroll 8
    for (int d = lane; d < DIM; d += 32) s += x_s[d] * wr[d];
    #pragma unroll
    for (int o = 16; o > 0; o >>= 1) s += __shfl_xor_sync(0xFFFFFFFFu, s, o);
    if (lane == 0) logit_s[w] = s + bg[w];
    __syncthreads();

    float g[NKF];
    float mx = -1e30f;
    #pragma unroll
    for (int k = 0; k < NKF; k++) { g[k] = logit_s[k]; mx = fmaxf(mx, g[k]); }
    float sum = 0.f;
    #pragma unroll
    for (int k = 0; k < NKF; k++) { g[k] = expf(g[k] - mx); sum += g[k]; }
    float inv = 1.f / sum;
    #pragma unroll
    for (int k = 0; k < NKF; k++) g[k] *= inv;
    if (tid < NKF) g_gate[n * NKF + tid] = g[tid];

    __half2* xt = reinterpret_cast<__half2*>(g_Xt + (size_t)n * KTOT);
    #pragma unroll
    for (int i = 0; i < 16; i++) {
        int idx2 = tid + i * 256;              // [0, 4096)
        int k = idx2 >> 9;
        int d = (idx2 & 511) * 2;
        xt[idx2] = __floats2half2_rn(g[k] * x_s[d], g[k] * x_s[d + 1]);
    }
}

// ---------------- kernel 3: facet-balance scalar (deterministic) ------------
__global__ void __launch_bounds__(256) balance_kernel(float* __restrict__ out,
                                                      int out_size) {
    __shared__ float red[256];
    int tid = threadIdx.x;
    float s = 0.f;
    for (int i = tid; i < NTOK * NKF; i += 256) s += g_gate[i];
    red[tid] = s;
    __syncthreads();
    for (int o = 128; o > 0; o >>= 1) {
        if (tid < o) red[tid] += red[tid + o];
        __syncthreads();
    }
    if (tid == 0) {
        float mean = red[0] / (float)(NTOK * NKF);
        float d = mean - 1.0f / NKF;
        out[out_size - 1] = d * d;
    }
}

// ---------------- kernel 4: fused HMMA GEMM + woven Wf conversion -----------
// C[128 tok x 128 voc] per CTA, 8 warps (4 M x 2 N of 32x64 warp tiles),
// 2 CTAs/SM. The first NPROD CTAs (all wave-1 resident) each convert one
// future panel fp32->fp16, woven across the 128 mainloop iterations
// (independent LDG->cvt->STG, off the MMA critical path). Consumers of
// panels >= MINI spin once at entry on the panel flag (producers are
// strictly lower-bid and resident -> deadlock-free).
__global__ void __launch_bounds__(256, 2) gemm_kernel(const float* __restrict__ Wf,
                                                      const float* __restrict__ bf,
                                                      float* __restrict__ out) {
    extern __shared__ char smem[];
    uint32_t sb = smem_u32(smem);
    float* bias_s = reinterpret_cast<float*>(smem + SM_BIAS);

    int tid = threadIdx.x;
    int wid = tid >> 5, lane = tid & 31;
    int wm = wid >> 1, wn = wid & 1;            // warp coords: 4 x 2
    int tb = blockIdx.x * MT;                   // token base
    int vb = blockIdx.y * NV;                   // vocab base

    int lb = blockIdx.x + (blockIdx.y << 3);    // linear bid (x fastest)
    bool prod = (lb < NPROD);
    int p = MINI + lb;                          // panel this CTA converts

    // ---- consumer handshake: wait for this CTA's panel to be converted ----
    if (blockIdx.y >= MINI) {
        if (tid == 0) {
            while (*(volatile int*)&g_flags[blockIdx.y] == 0) {}
        }
        __syncthreads();
        __threadfence();                        // acquire
    }

    // bias tile -> smem
    #pragma unroll
    for (int i = 0; i < 4; i++) {
        int idx = tid + i * 256;                // [0, 1024)
        int k = idx >> 7, col = idx & 127;
        bias_s[idx] = bf[(size_t)k * VOC + vb + col];
    }

    // ---- producer helper (all 256 threads) ----
    auto load_stage = [&](int s, int it) {
        int kb = it * KT;
        uint32_t a_base = sb + SM_A(s);
        uint32_t b_base = sb + SM_B(s);
        #pragma unroll
        for (int i = 0; i < 4; i++) {           // A: 1024 16B chunks
            int lin = tid + i * 256;
            int r = lin >> 3, c = lin & 7;
            cp16(a_base + sw128(r * 128 + c * 16),
                 g_Xt + (size_t)(tb + r) * KTOT + kb + c * 8);
        }
        #pragma unroll
        for (int i = 0; i < 4; i++) {           // B: 1024 16B chunks
            int lin = tid + i * 256;
            int r = lin >> 3, c = lin & 7;
            cp16(b_base + sw128(r * 128 + c * 16),
                 g_Wf16T + (size_t)(vb + r) * KTOT + kb + c * 8);
        }
    };

    // prologue: fill STAGES-1 stages
    #pragma unroll
    for (int s = 0; s < STAGES - 1; s++) {
        load_stage(s, s);
        cp_commit();
    }

    float c[2][8][4];
    #pragma unroll
    for (int mt = 0; mt < 2; mt++)
        #pragma unroll
        for (int nt = 0; nt < 8; nt++)
            #pragma unroll
            for (int j = 0; j < 4; j++) c[mt][nt][j] = 0.f;

    int stage = 0;
    for (int it = 0; it < NKIT; it++) {
        cp_wait<STAGES - 2>();
        __syncthreads();

        uint32_t a_base = sb + SM_A(stage);
        uint32_t b_base = sb + SM_B(stage);
        #pragma unroll
        for (int k16 = 0; k16 < 4; k16++) {
            uint32_t af[2][4];
            #pragma unroll
            for (int mt = 0; mt < 2; mt++) {
                int row = wm * 32 + mt * 16 + (lane & 15);
                uint32_t addr = a_base +
                    sw128(row * 128 + k16 * 32 + (lane >> 4) * 16);
                ldm_x4(af[mt][0], af[mt][1], af[mt][2], af[mt][3], addr);
            }
            uint32_t bfr[4][4];
            #pragma unroll
            for (int nt2 = 0; nt2 < 4; nt2++) {
                int tq = lane >> 3;
                int n_off = (tq >> 1) * 8 + (lane & 7);
                int k_half = tq & 1;
                int row = wn * 64 + nt2 * 16 + n_off;
                uint32_t addr = b_base +
                    sw128(row * 128 + k16 * 32 + k_half * 16);
                ldm_x4(bfr[nt2][0], bfr[nt2][1], bfr[nt2][2], bfr[nt2][3], addr);
            }
            #pragma unroll
            for (int mt = 0; mt < 2; mt++)
                #pragma unroll
                for (int nt = 0; nt < 8; nt++)
                    mma16816(c[mt][nt], af[mt], &bfr[nt >> 1][(nt & 1) * 2]);
        }

        int nxt = it + STAGES - 1;
        if (nxt < NKIT) {
            load_stage((stage + STAGES - 1) % STAGES, nxt);
        }
        cp_commit();
        stage = (stage + 1) % STAGES;

        // ---- woven conversion: 4 chunks (64 halves) per thread per iter ----
        if (prod) {
            size_t pbase = (size_t)p * (NV * KTOT);     // half offset of panel
            int cb = it * 1024 + tid;                   // chunk id base
            #pragma unroll
            for (int j = 0; j < 4; j++) {
                int cc = cb + j * 256;                  // [0, 131072)
                size_t o = (size_t)cc * 8;              // half offset in panel
                int pv = (int)(o >> 13);
                int rem = (int)(o & (KTOT - 1));
                int k = rem >> 10;
                int d = rem & (DIM - 1);
                const float4* src = reinterpret_cast<const float4*>(
                    Wf + ((size_t)k * VOC + p * NV + pv) * DIM + d);
                float4 ua = src[0], ub = src[1];
                __half2 h[4];
                h[0] = __floats2half2_rn(ua.x, ua.y);
                h[1] = __floats2half2_rn(ua.z, ua.w);
                h[2] = __floats2half2_rn(ub.x, ub.y);
                h[3] = __floats2half2_rn(ub.z, ub.w);
                *reinterpret_cast<uint4*>(g_Wf16T + pbase + o) =
                    *reinterpret_cast<uint4*>(h);
            }
        }
    }

    // ---- producer flag release (panel fully written) ----
    if (prod) {
        __threadfence();
        __syncthreads();
        if (tid == 0) atomicExch(&g_flags[p], 1);
    }

    // ---- epilogue: out = C + sum_k g[tok,k] * bf[k,col] ----
    #pragma unroll
    for (int mt = 0; mt < 2; mt++) {
        int tok0 = tb + wm * 32 + mt * 16 + (lane >> 2);
        int tok1 = tok0 + 8;
        float gA[8], gB[8];
        #pragma unroll
        for (int k = 0; k < 8; k++) {
            gA[k] = g_gate[tok0 * NKF + k];
            gB[k] = g_gate[tok1 * NKF + k];
        }
        float* r0 = out + (size_t)tok0 * VOC + vb;
        float* r1 = out + (size_t)tok1 * VOC + vb;
        #pragma unroll
        for (int nt = 0; nt < 8; nt++) {
            int col = wn * 64 + nt * 8 + (lane & 3) * 2;
            float b00 = 0.f, b01 = 0.f, b10 = 0.f, b11 = 0.f;
            #pragma unroll
            for (int k = 0; k < 8; k++) {
                float f0 = bias_s[k * 128 + col];
                float f1 = bias_s[k * 128 + col + 1];
                b00 += gA[k] * f0; b01 += gA[k] * f1;
                b10 += gB[k] * f0; b11 += gB[k] * f1;
            }
            float2 v0 = {c[mt][nt][0] + b00, c[mt][nt][1] + b01};
            float2 v1 = {c[mt][nt][2] + b10, c[mt][nt][3] + b11};
            *reinterpret_cast<float2*>(r0 + col) = v0;
            *reinterpret_cast<float2*>(r1 + col) = v1;
        }
    }
}

// ---------------- launch -----------------------------------------------------
extern "C" void kernel_launch(void* const* d_in, const int* in_sizes, int n_in,
                              void* d_out, int out_size) {
    const float* x  = (const float*)d_in[0];
    const float* Wg = (const float*)d_in[1];
    const float* bg = (const float*)d_in[2];
    const float* Wf = (const float*)d_in[3];
    const float* bf = (const float*)d_in[4];
    float* out = (float*)d_out;

    cudaFuncSetAttribute(gemm_kernel, cudaFuncAttributeMaxDynamicSharedMemorySize,
                         SMEM_TOTAL);

    gate_kernel<<<NTOK, 256>>>(x, Wg, bg);       // also clears panel flags
    // mini convert: panels 0..MINI-1 = MINI*NV*KTOT/8 chunks / 256 per block
    convert_wf_kernel<<<(unsigned)((size_t)MINI * NV * KTOT / 8 / 256), 256>>>(Wf);
    balance_kernel<<<1, 256>>>(out, out_size);
    dim3 grid(NTOK / MT, VOC / NV);
    gemm_kernel<<<grid, 256, SMEM_TOTAL>>>(Wf, bf, out);
}

// round 16
// speedup vs baseline: 1.0412x; 1.0412x over previous
#include <cuda_runtime.h>
#include <cuda_fp16.h>
#include <cstdint>
#include <cstddef>

// Problem dims
#define NTOK 1024
#define DIM  1024
#define VOC  32000
#define NKF  8
#define KTOT (NKF * DIM)            // 8192

// GEMM tiling
#define MT 128                      // token rows per CTA
#define NV 128                      // vocab cols per CTA
#define KT 64                       // k halves per stage (= 128 B per row, SW128)
#define NKIT (KTOT / KT)            // 128 k-iterations
#define STAGES 3

// convert grid split
#define NCONV_BLOCKS 128000         // VOC*KTOT/8/256 chunks
#define NTOTAL_BLOCKS (NCONV_BLOCKS + NTOK)

// SMEM layout (dynamic, gemm)
#define SM_BIAS 0                                   // 8*128 floats = 4096 B
#define SM_TILE 4096
#define STAGE_A_BYTES (MT * 128)                    // 16384
#define STAGE_B_BYTES (NV * 128)                    // 16384
#define STAGE_BYTES (STAGE_A_BYTES + STAGE_B_BYTES) // 32768
#define SM_A(s) (SM_TILE + (s) * STAGE_BYTES)
#define SM_B(s) (SM_A(s) + STAGE_A_BYTES)
#define SMEM_TOTAL (SM_TILE + STAGES * STAGE_BYTES) // 102400 -> 2 CTAs/SM

// ---------------- static device scratch (no cudaMalloc allowed) -------------
__device__ __align__(1024) __half g_Wf16T[(size_t)VOC * KTOT];   // [v][k*D+d]
__device__ __align__(1024) __half g_Xt[(size_t)NTOK * KTOT];     // [n][k*D+d]
__device__ float g_gate[NTOK * NKF];

// ---------------- PTX helpers ------------------------------------------------
__device__ __forceinline__ uint32_t smem_u32(const void* p) {
    uint32_t a;
    asm("{ .reg .u64 t; cvta.to.shared.u64 t, %1; cvt.u32.u64 %0, t; }"
        : "=r"(a) : "l"(p));
    return a;
}
__device__ __forceinline__ void cp16(uint32_t dst, const void* src) {
    asm volatile("cp.async.cg.shared.global [%0], [%1], 16;"
                 :: "r"(dst), "l"(__cvta_generic_to_global(src)) : "memory");
}
__device__ __forceinline__ void cp_commit() {
    asm volatile("cp.async.commit_group;" ::: "memory");
}
template <int N>
__device__ __forceinline__ void cp_wait() {
    asm volatile("cp.async.wait_group %0;" :: "n"(N) : "memory");
}
__device__ __forceinline__ void ldm_x4(uint32_t& r0, uint32_t& r1, uint32_t& r2,
                                       uint32_t& r3, uint32_t addr) {
    asm volatile("ldmatrix.sync.aligned.m8n8.x4.shared.b16 {%0,%1,%2,%3}, [%4];"
                 : "=r"(r0), "=r"(r1), "=r"(r2), "=r"(r3) : "r"(addr));
}
__device__ __forceinline__ void mma16816(float* c, const uint32_t* a,
                                         const uint32_t* b) {
    asm volatile(
        "mma.sync.aligned.m16n8k16.row.col.f32.f16.f16.f32 "
        "{%0,%1,%2,%3}, {%4,%5,%6,%7}, {%8,%9}, {%0,%1,%2,%3};"
        : "+f"(c[0]), "+f"(c[1]), "+f"(c[2]), "+f"(c[3])
        : "r"(a[0]), "r"(a[1]), "r"(a[2]), "r"(a[3]), "r"(b[0]), "r"(b[1]));
}
__device__ __forceinline__ uint32_t sw128(uint32_t off) {
    return off ^ ((off >> 3) & 0x70);
}

// ---------------- kernel 1: fused Wf convert + gate softmax ------------------
// Blocks [0, NCONV_BLOCKS): Wf fp32 -> fp16 transposed to [v][k*D+d].
// Blocks [NCONV_BLOCKS, +NTOK): gate softmax + Xt = g*x (fp16).
// The two halves touch disjoint data; merging removes one launch + its
// serialization against the DRAM-roofline convert.
__global__ void __launch_bounds__(256) prep_kernel(const float* __restrict__ Wf,
                                                   const float* __restrict__ x,
                                                   const float* __restrict__ Wg,
                                                   const float* __restrict__ bg) {
    __shared__ float x_s[DIM];
    __shared__ float logit_s[NKF];
    int tid = threadIdx.x;

    if (blockIdx.x < NCONV_BLOCKS) {
        // ---- convert path (identical math to the R14 convert kernel) ----
        size_t gid = (size_t)blockIdx.x * 256 + tid;       // one 8-half chunk
        size_t o = gid * 8;            // output half index
        int v = (int)(o >> 13);        // / 8192
        int rem = (int)(o & (KTOT - 1));
        int k = rem >> 10;
        int d = rem & (DIM - 1);
        const float4* src = reinterpret_cast<const float4*>(
            Wf + ((size_t)k * VOC + v) * DIM + d);
        float4 a = src[0], b = src[1];
        __half2 h[4];
        h[0] = __floats2half2_rn(a.x, a.y);
        h[1] = __floats2half2_rn(a.z, a.w);
        h[2] = __floats2half2_rn(b.x, b.y);
        h[3] = __floats2half2_rn(b.z, b.w);
        *reinterpret_cast<uint4*>(g_Wf16T + o) = *reinterpret_cast<uint4*>(h);
        return;
    }

    // ---- gate path ----
    int n = blockIdx.x - NCONV_BLOCKS;
    int w = tid >> 5, lane = tid & 31;

    const float* xr = x + (size_t)n * DIM;
    for (int i = tid; i < DIM; i += 256) x_s[i] = xr[i];
    __syncthreads();

    float s = 0.f;
    const float* wr = Wg + w * DIM;
    #pragma unroll 8
    for (int d = lane; d < DIM; d += 32) s += x_s[d] * wr[d];
    #pragma unroll
    for (int o = 16; o > 0; o >>= 1) s += __shfl_xor_sync(0xFFFFFFFFu, s, o);
    if (lane == 0) logit_s[w] = s + bg[w];
    __syncthreads();

    float g[NKF];
    float mx = -1e30f;
    #pragma unroll
    for (int k = 0; k < NKF; k++) { g[k] = logit_s[k]; mx = fmaxf(mx, g[k]); }
    float sum = 0.f;
    #pragma unroll
    for (int k = 0; k < NKF; k++) { g[k] = expf(g[k] - mx); sum += g[k]; }
    float inv = 1.f / sum;
    #pragma unroll
    for (int k = 0; k < NKF; k++) g[k] *= inv;
    if (tid < NKF) g_gate[n * NKF + tid] = g[tid];

    __half2* xt = reinterpret_cast<__half2*>(g_Xt + (size_t)n * KTOT);
    #pragma unroll
    for (int i = 0; i < 16; i++) {
        int idx2 = tid + i * 256;              // [0, 4096)
        int k = idx2 >> 9;
        int d = (idx2 & 511) * 2;
        xt[idx2] = __floats2half2_rn(g[k] * x_s[d], g[k] * x_s[d + 1]);
    }
}

// ---------------- kernel 2: fused HMMA GEMM + gated-bias epilogue -----------
// C[128 tok x 128 voc] per CTA, 8 warps (4 M x 2 N of 32x64 warp tiles),
// 2 CTAs/SM. Block (0,0) additionally computes the facet-balance scalar
// in its prologue (g_gate is complete before this kernel launches); the
// ~5us of extra work is hidden under the 1.17ms wave.
__global__ void __launch_bounds__(256, 2) gemm_kernel(const float* __restrict__ bf,
                                                      float* __restrict__ out,
                                                      int out_size) {
    extern __shared__ char smem[];
    uint32_t sb = smem_u32(smem);
    float* bias_s = reinterpret_cast<float*>(smem + SM_BIAS);

    int tid = threadIdx.x;
    int wid = tid >> 5, lane = tid & 31;
    int wm = wid >> 1, wn = wid & 1;            // warp coords: 4 x 2
    int tb = blockIdx.x * MT;                   // token base
    int vb = blockIdx.y * NV;                   // vocab base

    // ---- balance scalar (block (0,0) only; identical tree reduction) ----
    if (blockIdx.x == 0 && blockIdx.y == 0) {
        __shared__ float red[256];
        float s = 0.f;
        for (int i = tid; i < NTOK * NKF; i += 256) s += g_gate[i];
        red[tid] = s;
        __syncthreads();
        for (int o = 128; o > 0; o >>= 1) {
            if (tid < o) red[tid] += red[tid + o];
            __syncthreads();
        }
        if (tid == 0) {
            float mean = red[0] / (float)(NTOK * NKF);
            float d = mean - 1.0f / NKF;
            out[out_size - 1] = d * d;
        }
        __syncthreads();
    }

    // bias tile -> smem
    #pragma unroll
    for (int i = 0; i < 4; i++) {
        int idx = tid + i * 256;                // [0, 1024)
        int k = idx >> 7, col = idx & 127;
        bias_s[idx] = bf[(size_t)k * VOC + vb + col];
    }

    // ---- producer helper (all 256 threads) ----
    auto load_stage = [&](int s, int it) {
        int kb = it * KT;
        uint32_t a_base = sb + SM_A(s);
        uint32_t b_base = sb + SM_B(s);
        #pragma unroll
        for (int i = 0; i < 4; i++) {           // A: 1024 16B chunks
            int lin = tid + i * 256;
            int r = lin >> 3, c = lin & 7;
            cp16(a_base + sw128(r * 128 + c * 16),
                 g_Xt + (size_t)(tb + r) * KTOT + kb + c * 8);
        }
        #pragma unroll
        for (int i = 0; i < 4; i++) {           // B: 1024 16B chunks
            int lin = tid + i * 256;
            int r = lin >> 3, c = lin & 7;
            cp16(b_base + sw128(r * 128 + c * 16),
                 g_Wf16T + (size_t)(vb + r) * KTOT + kb + c * 8);
        }
    };

    // prologue: fill STAGES-1 stages
    #pragma unroll
    for (int s = 0; s < STAGES - 1; s++) {
        load_stage(s, s);
        cp_commit();
    }

    float c[2][8][4];
    #pragma unroll
    for (int mt = 0; mt < 2; mt++)
        #pragma unroll
        for (int nt = 0; nt < 8; nt++)
            #pragma unroll
            for (int j = 0; j < 4; j++) c[mt][nt][j] = 0.f;

    int stage = 0;
    for (int it = 0; it < NKIT; it++) {
        cp_wait<STAGES - 2>();
        __syncthreads();

        uint32_t a_base = sb + SM_A(stage);
        uint32_t b_base = sb + SM_B(stage);
        #pragma unroll
        for (int k16 = 0; k16 < 4; k16++) {
            uint32_t af[2][4];
            #pragma unroll
            for (int mt = 0; mt < 2; mt++) {
                int row = wm * 32 + mt * 16 + (lane & 15);
                uint32_t addr = a_base +
                    sw128(row * 128 + k16 * 32 + (lane >> 4) * 16);
                ldm_x4(af[mt][0], af[mt][1], af[mt][2], af[mt][3], addr);
            }
            uint32_t bfr[4][4];
            #pragma unroll
            for (int nt2 = 0; nt2 < 4; nt2++) {
                int tq = lane >> 3;
                int n_off = (tq >> 1) * 8 + (lane & 7);
                int k_half = tq & 1;
                int row = wn * 64 + nt2 * 16 + n_off;
                uint32_t addr = b_base +
                    sw128(row * 128 + k16 * 32 + k_half * 16);
                ldm_x4(bfr[nt2][0], bfr[nt2][1], bfr[nt2][2], bfr[nt2][3], addr);
            }
            #pragma unroll
            for (int mt = 0; mt < 2; mt++)
                #pragma unroll
                for (int nt = 0; nt < 8; nt++)
                    mma16816(c[mt][nt], af[mt], &bfr[nt >> 1][(nt & 1) * 2]);
        }

        int nxt = it + STAGES - 1;
        if (nxt < NKIT) {
            load_stage((stage + STAGES - 1) % STAGES, nxt);
        }
        cp_commit();
        stage = (stage + 1) % STAGES;
    }

    // ---- epilogue: out = C + sum_k g[tok,k] * bf[k,col] ----
    #pragma unroll
    for (int mt = 0; mt < 2; mt++) {
        int tok0 = tb + wm * 32 + mt * 16 + (lane >> 2);
        int tok1 = tok0 + 8;
        float gA[8], gB[8];
        #pragma unroll
        for (int k = 0; k < 8; k++) {
            gA[k] = g_gate[tok0 * NKF + k];
            gB[k] = g_gate[tok1 * NKF + k];
        }
        float* r0 = out + (size_t)tok0 * VOC + vb;
        float* r1 = out + (size_t)tok1 * VOC + vb;
        #pragma unroll
        for (int nt = 0; nt < 8; nt++) {
            int col = wn * 64 + nt * 8 + (lane & 3) * 2;
            float b00 = 0.f, b01 = 0.f, b10 = 0.f, b11 = 0.f;
            #pragma unroll
            for (int k = 0; k < 8; k++) {
                float f0 = bias_s[k * 128 + col];
                float f1 = bias_s[k * 128 + col + 1];
                b00 += gA[k] * f0; b01 += gA[k] * f1;
                b10 += gB[k] * f0; b11 += gB[k] * f1;
            }
            float2 v0 = {c[mt][nt][0] + b00, c[mt][nt][1] + b01};
            float2 v1 = {c[mt][nt][2] + b10, c[mt][nt][3] + b11};
            *reinterpret_cast<float2*>(r0 + col) = v0;
            *reinterpret_cast<float2*>(r1 + col) = v1;
        }
    }
}

// ---------------- launch -----------------------------------------------------
extern "C" void kernel_launch(void* const* d_in, const int* in_sizes, int n_in,
                              void* d_out, int out_size) {
    const float* x  = (const float*)d_in[0];
    const float* Wg = (const float*)d_in[1];
    const float* bg = (const float*)d_in[2];
    const float* Wf = (const float*)d_in[3];
    const float* bf = (const float*)d_in[4];
    float* out = (float*)d_out;

    cudaFuncSetAttribute(gemm_kernel, cudaFuncAttributeMaxDynamicSharedMemorySize,
                         SMEM_TOTAL);

    prep_kernel<<<NTOTAL_BLOCKS, 256>>>(Wf, x, Wg, bg);
    dim3 grid(NTOK / MT, VOC / NV);
    gemm_kernel<<<grid, 256, SMEM_TOTAL>>>(bf, out, out_size);
}

// round 17
// speedup vs baseline: 1.0951x; 1.0518x over previous
#include <cuda_runtime.h>
#include <cuda_fp16.h>
#include <cstdint>
#include <cstddef>

// Problem dims
#define NTOK 1024
#define DIM  1024
#define VOC  32000
#define NKF  8
#define KTOT (NKF * DIM)            // 8192

// GEMM tiling
#define MT 128                      // token rows per CTA
#define NV 128                      // vocab cols per CTA
#define KT 64                       // k halves per stage (= 128 B per row, SW128)
#define NKIT (KTOT / KT)            // 128 k-iterations
#define STAGES 3
#define NPAN (VOC / NV)             // 250 vocab panels
#define NTILE ((NTOK / MT) * NPAN)  // 2000 gemm tiles

// in-grid conversion split
#define MINI 26                     // panels converted in prep (covers wave-1 consumers)
#define NCONVCTA 112                // converter CTAs at grid front
#define PANPERC 2                   // panels per converter CTA (112*2 = 224 = 250-26)
#define CHUNKS_PER_PANEL (NV * KTOT / 8)     // 131072 8-half chunks
#define MINI_BLOCKS (MINI * CHUNKS_PER_PANEL / 256)   // 13312
#define PREP_BLOCKS (MINI_BLOCKS + NTOK)

// SMEM layout (dynamic, gemm)
#define SM_BIAS 0                                   // 8*128 floats = 4096 B
#define SM_TILE 4096
#define STAGE_A_BYTES (MT * 128)                    // 16384
#define STAGE_B_BYTES (NV * 128)                    // 16384
#define STAGE_BYTES (STAGE_A_BYTES + STAGE_B_BYTES) // 32768
#define SM_A(s) (SM_TILE + (s) * STAGE_BYTES)
#define SM_B(s) (SM_A(s) + STAGE_A_BYTES)
#define SMEM_TOTAL (SM_TILE + STAGES * STAGE_BYTES) // 102400 -> 2 CTAs/SM

// ---------------- static device scratch (no cudaMalloc allowed) -------------
__device__ __align__(1024) __half g_Wf16T[(size_t)VOC * KTOT];   // [v][k*D+d]
__device__ __align__(1024) __half g_Xt[(size_t)NTOK * KTOT];     // [n][k*D+d]
__device__ float g_gate[NTOK * NKF];
__device__ int g_flags[256];                                     // per-panel ready

// ---------------- PTX helpers ------------------------------------------------
__device__ __forceinline__ uint32_t smem_u32(const void* p) {
    uint32_t a;
    asm("{ .reg .u64 t; cvta.to.shared.u64 t, %1; cvt.u32.u64 %0, t; }"
        : "=r"(a) : "l"(p));
    return a;
}
__device__ __forceinline__ void cp16(uint32_t dst, const void* src) {
    asm volatile("cp.async.cg.shared.global [%0], [%1], 16;"
                 :: "r"(dst), "l"(__cvta_generic_to_global(src)) : "memory");
}
__device__ __forceinline__ void cp_commit() {
    asm volatile("cp.async.commit_group;" ::: "memory");
}
template <int N>
__device__ __forceinline__ void cp_wait() {
    asm volatile("cp.async.wait_group %0;" :: "n"(N) : "memory");
}
__device__ __forceinline__ void ldm_x4(uint32_t& r0, uint32_t& r1, uint32_t& r2,
                                       uint32_t& r3, uint32_t addr) {
    asm volatile("ldmatrix.sync.aligned.m8n8.x4.shared.b16 {%0,%1,%2,%3}, [%4];"
                 : "=r"(r0), "=r"(r1), "=r"(r2), "=r"(r3) : "r"(addr));
}
__device__ __forceinline__ void mma16816(float* c, const uint32_t* a,
                                         const uint32_t* b) {
    asm volatile(
        "mma.sync.aligned.m16n8k16.row.col.f32.f16.f16.f32 "
        "{%0,%1,%2,%3}, {%4,%5,%6,%7}, {%8,%9}, {%0,%1,%2,%3};"
        : "+f"(c[0]), "+f"(c[1]), "+f"(c[2]), "+f"(c[3])
        : "r"(a[0]), "r"(a[1]), "r"(a[2]), "r"(a[3]), "r"(b[0]), "r"(b[1]));
}
__device__ __forceinline__ uint32_t sw128(uint32_t off) {
    return off ^ ((off >> 3) & 0x70);
}

// shared convert helper: one 8-half chunk at global half-offset o
__device__ __forceinline__ void convert_chunk(const float* __restrict__ Wf,
                                              size_t o) {
    int v = (int)(o >> 13);            // / 8192
    int rem = (int)(o & (KTOT - 1));
    int k = rem >> 10;
    int d = rem & (DIM - 1);
    const float4* src = reinterpret_cast<const float4*>(
        Wf + ((size_t)k * VOC + v) * DIM + d);
    float4 a = src[0], b = src[1];
    __half2 h[4];
    h[0] = __floats2half2_rn(a.x, a.y);
    h[1] = __floats2half2_rn(a.z, a.w);
    h[2] = __floats2half2_rn(b.x, b.y);
    h[3] = __floats2half2_rn(b.z, b.w);
    *reinterpret_cast<uint4*>(g_Wf16T + o) = *reinterpret_cast<uint4*>(h);
}

// ---------------- kernel 1: prep = mini convert + gate softmax ---------------
// Blocks [0, MINI_BLOCKS): convert panels 0..MINI-1 (the wave-1 consumer set).
// Blocks [MINI_BLOCKS, +NTOK): gate softmax + Xt = g*x (fp16); block 0 of the
// gate range also clears the panel flags.
__global__ void __launch_bounds__(256) prep_kernel(const float* __restrict__ Wf,
                                                   const float* __restrict__ x,
                                                   const float* __restrict__ Wg,
                                                   const float* __restrict__ bg) {
    __shared__ float x_s[DIM];
    __shared__ float logit_s[NKF];
    int tid = threadIdx.x;

    if (blockIdx.x < MINI_BLOCKS) {
        size_t gid = (size_t)blockIdx.x * 256 + tid;
        convert_chunk(Wf, gid * 8);
        return;
    }

    // ---- gate path ----
    int n = blockIdx.x - MINI_BLOCKS;
    int w = tid >> 5, lane = tid & 31;

    if (n == 0) g_flags[tid] = 0;      // reset panel flags every launch

    const float* xr = x + (size_t)n * DIM;
    for (int i = tid; i < DIM; i += 256) x_s[i] = xr[i];
    __syncthreads();

    float s = 0.f;
    const float* wr = Wg + w * DIM;
    #pragma unroll 8
    for (int d = lane; d < DIM; d += 32) s += x_s[d] * wr[d];
    #pragma unroll
    for (int o = 16; o > 0; o >>= 1) s += __shfl_xor_sync(0xFFFFFFFFu, s, o);
    if (lane == 0) logit_s[w] = s + bg[w];
    __syncthreads();

    float g[NKF];
    float mx = -1e30f;
    #pragma unroll
    for (int k = 0; k < NKF; k++) { g[k] = logit_s[k]; mx = fmaxf(mx, g[k]); }
    float sum = 0.f;
    #pragma unroll
    for (int k = 0; k < NKF; k++) { g[k] = expf(g[k] - mx); sum += g[k]; }
    float inv = 1.f / sum;
    #pragma unroll
    for (int k = 0; k < NKF; k++) g[k] *= inv;
    if (tid < NKF) g_gate[n * NKF + tid] = g[tid];

    __half2* xt = reinterpret_cast<__half2*>(g_Xt + (size_t)n * KTOT);
    #pragma unroll
    for (int i = 0; i < 16; i++) {
        int idx2 = tid + i * 256;              // [0, 4096)
        int k = idx2 >> 9;
        int d = (idx2 & 511) * 2;
        xt[idx2] = __floats2half2_rn(g[k] * x_s[d], g[k] * x_s[d + 1]);
    }
}

// ---------------- kernel 2: gemm grid = converters + HMMA tiles --------------
// bids [0, NCONVCTA): each converts PANPERC panels (26..249) and sets flags,
// then retires, returning its SM slot to the gemm. bids >= NCONVCTA: the R14
// HMMA tile (panel-major, token-fastest). Wave-1 gemm CTAs only touch panels
// < MINI (pre-converted); later CTAs check the flag (normally already set).
__global__ void __launch_bounds__(256, 2) gemm_kernel(const float* __restrict__ Wf,
                                                      const float* __restrict__ bf,
                                                      float* __restrict__ out,
                                                      int out_size) {
    extern __shared__ char smem[];
    uint32_t sb = smem_u32(smem);
    float* bias_s = reinterpret_cast<float*>(smem + SM_BIAS);

    int tid = threadIdx.x;
    int bid = blockIdx.x;

    // ---- converter CTAs ----
    if (bid < NCONVCTA) {
        #pragma unroll 1
        for (int pp = 0; pp < PANPERC; pp++) {
            int p = MINI + bid * PANPERC + pp;
            size_t pbase = (size_t)p * (NV * KTOT);     // panel half-offset
            #pragma unroll 4
            for (int i = 0; i < CHUNKS_PER_PANEL / 256; i++) {
                int cc = tid + i * 256;
                convert_chunk(Wf, pbase + (size_t)cc * 8);
            }
            __threadfence();
            __syncthreads();
            if (tid == 0) atomicExch(&g_flags[p], 1);
        }
        return;
    }

    int lt = bid - NCONVCTA;            // 0..1999, token fastest
    int pan = lt >> 3;
    int tx = lt & 7;
    int tb = tx * MT;                   // token base
    int vb = pan * NV;                  // vocab base
    int wid = tid >> 5, lane = tid & 31;
    int wm = wid >> 1, wn = wid & 1;    // warp coords: 4 x 2

    // ---- consumer handshake (panels >= MINI; normally already converted) ----
    if (pan >= MINI) {
        if (tid == 0) {
            while (*(volatile int*)&g_flags[pan] == 0) {}
        }
        __syncthreads();
        __threadfence();                // acquire
    }

    // ---- balance scalar (first gemm CTA only) ----
    if (lt == 0) {
        __shared__ float red[256];
        float s = 0.f;
        for (int i = tid; i < NTOK * NKF; i += 256) s += g_gate[i];
        red[tid] = s;
        __syncthreads();
        for (int o = 128; o > 0; o >>= 1) {
            if (tid < o) red[tid] += red[tid + o];
            __syncthreads();
        }
        if (tid == 0) {
            float mean = red[0] / (float)(NTOK * NKF);
            float d = mean - 1.0f / NKF;
            out[out_size - 1] = d * d;
        }
        __syncthreads();
    }

    // bias tile -> smem
    #pragma unroll
    for (int i = 0; i < 4; i++) {
        int idx = tid + i * 256;                // [0, 1024)
        int k = idx >> 7, col = idx & 127;
        bias_s[idx] = bf[(size_t)k * VOC + vb + col];
    }

    // ---- producer helper (all 256 threads) ----
    auto load_stage = [&](int s, int it) {
        int kb = it * KT;
        uint32_t a_base = sb + SM_A(s);
        uint32_t b_base = sb + SM_B(s);
        #pragma unroll
        for (int i = 0; i < 4; i++) {           // A: 1024 16B chunks
            int lin = tid + i * 256;
            int r = lin >> 3, c = lin & 7;
            cp16(a_base + sw128(r * 128 + c * 16),
                 g_Xt + (size_t)(tb + r) * KTOT + kb + c * 8);
        }
        #pragma unroll
        for (int i = 0; i < 4; i++) {           // B: 1024 16B chunks
            int lin = tid + i * 256;
            int r = lin >> 3, c = lin & 7;
            cp16(b_base + sw128(r * 128 + c * 16),
                 g_Wf16T + (size_t)(vb + r) * KTOT + kb + c * 8);
        }
    };

    // prologue: fill STAGES-1 stages
    #pragma unroll
    for (int s = 0; s < STAGES - 1; s++) {
        load_stage(s, s);
        cp_commit();
    }

    float c[2][8][4];
    #pragma unroll
    for (int mt = 0; mt < 2; mt++)
        #pragma unroll
        for (int nt = 0; nt < 8; nt++)
            #pragma unroll
            for (int j = 0; j < 4; j++) c[mt][nt][j] = 0.f;

    int stage = 0;
    for (int it = 0; it < NKIT; it++) {
        cp_wait<STAGES - 2>();
        __syncthreads();

        uint32_t a_base = sb + SM_A(stage);
        uint32_t b_base = sb + SM_B(stage);
        #pragma unroll
        for (int k16 = 0; k16 < 4; k16++) {
            uint32_t af[2][4];
            #pragma unroll
            for (int mt = 0; mt < 2; mt++) {
                int row = wm * 32 + mt * 16 + (lane & 15);
                uint32_t addr = a_base +
                    sw128(row * 128 + k16 * 32 + (lane >> 4) * 16);
                ldm_x4(af[mt][0], af[mt][1], af[mt][2], af[mt][3], addr);
            }
            uint32_t bfr[4][4];
            #pragma unroll
            for (int nt2 = 0; nt2 < 4; nt2++) {
                int tq = lane >> 3;
                int n_off = (tq >> 1) * 8 + (lane & 7);
                int k_half = tq & 1;
                int row = wn * 64 + nt2 * 16 + n_off;
                uint32_t addr = b_base +
                    sw128(row * 128 + k16 * 32 + k_half * 16);
                ldm_x4(bfr[nt2][0], bfr[nt2][1], bfr[nt2][2], bfr[nt2][3], addr);
            }
            #pragma unroll
            for (int mt = 0; mt < 2; mt++)
                #pragma unroll
                for (int nt = 0; nt < 8; nt++)
                    mma16816(c[mt][nt], af[mt], &bfr[nt >> 1][(nt & 1) * 2]);
        }

        int nxt = it + STAGES - 1;
        if (nxt < NKIT) {
            load_stage((stage + STAGES - 1) % STAGES, nxt);
        }
        cp_commit();
        stage = (stage + 1) % STAGES;
    }

    // ---- epilogue: out = C + sum_k g[tok,k] * bf[k,col] ----
    #pragma unroll
    for (int mt = 0; mt < 2; mt++) {
        int tok0 = tb + wm * 32 + mt * 16 + (lane >> 2);
        int tok1 = tok0 + 8;
        float gA[8], gB[8];
        #pragma unroll
        for (int k = 0; k < 8; k++) {
            gA[k] = g_gate[tok0 * NKF + k];
            gB[k] = g_gate[tok1 * NKF + k];
        }
        float* r0 = out + (size_t)tok0 * VOC + vb;
        float* r1 = out + (size_t)tok1 * VOC + vb;
        #pragma unroll
        for (int nt = 0; nt < 8; nt++) {
            int col = wn * 64 + nt * 8 + (lane & 3) * 2;
            float b00 = 0.f, b01 = 0.f, b10 = 0.f, b11 = 0.f;
            #pragma unroll
            for (int k = 0; k < 8; k++) {
                float f0 = bias_s[k * 128 + col];
                float f1 = bias_s[k * 128 + col + 1];
                b00 += gA[k] * f0; b01 += gA[k] * f1;
                b10 += gB[k] * f0; b11 += gB[k] * f1;
            }
            float2 v0 = {c[mt][nt][0] + b00, c[mt][nt][1] + b01};
            float2 v1 = {c[mt][nt][2] + b10, c[mt][nt][3] + b11};
            *reinterpret_cast<float2*>(r0 + col) = v0;
            *reinterpret_cast<float2*>(r1 + col) = v1;
        }
    }
}

// ---------------- launch -----------------------------------------------------
extern "C" void kernel_launch(void* const* d_in, const int* in_sizes, int n_in,
                              void* d_out, int out_size) {
    const float* x  = (const float*)d_in[0];
    const float* Wg = (const float*)d_in[1];
    const float* bg = (const float*)d_in[2];
    const float* Wf = (const float*)d_in[3];
    const float* bf = (const float*)d_in[4];
    float* out = (float*)d_out;

    cudaFuncSetAttribute(gemm_kernel, cudaFuncAttributeMaxDynamicSharedMemorySize,
                         SMEM_TOTAL);

    prep_kernel<<<PREP_BLOCKS, 256>>>(Wf, x, Wg, bg);
    gemm_kernel<<<NCONVCTA + NTILE, 256, SMEM_TOTAL>>>(Wf, bf, out, out_size);
}